// round 14
// baseline (speedup 1.0000x reference)
#include <cuda_runtime.h>
#include <cuda_bf16.h>
#include <cstdint>

#define DIM   2048
#define BSZ   2
#define SEQ   2048
#define NH    16
#define HD    128
#define MROWS (BSZ*SEQ)   /* 4096 */

typedef unsigned long long ull;

// ---- PTX helpers (baseline PTX only; no sm_103a-gated features) ----
__device__ __forceinline__ uint32_t smem_to_u32(const void* p) {
    uint32_t a;
    asm("{ .reg .u64 t; cvta.to.shared.u64 t, %1; cvt.u32.u64 %0, t; }" : "=r"(a) : "l"(p));
    return a;
}
__device__ __forceinline__ void ldsm4(uint32_t (&r)[4], uint32_t addr) {
    asm volatile("ldmatrix.sync.aligned.m8n8.x4.shared.b16 {%0,%1,%2,%3}, [%4];"
                 : "=r"(r[0]), "=r"(r[1]), "=r"(r[2]), "=r"(r[3]) : "r"(addr));
}
__device__ __forceinline__ void ldsm4t(uint32_t (&r)[4], uint32_t addr) {
    asm volatile("ldmatrix.sync.aligned.m8n8.x4.trans.shared.b16 {%0,%1,%2,%3}, [%4];"
                 : "=r"(r[0]), "=r"(r[1]), "=r"(r[2]), "=r"(r[3]) : "r"(addr));
}
__device__ __forceinline__ void mma_bf16(float (&d)[4], const uint32_t (&a)[4],
                                         uint32_t b0, uint32_t b1) {
    asm volatile("mma.sync.aligned.m16n8k16.row.col.f32.bf16.bf16.f32 "
                 "{%0,%1,%2,%3}, {%4,%5,%6,%7}, {%8,%9}, {%0,%1,%2,%3};"
                 : "+f"(d[0]), "+f"(d[1]), "+f"(d[2]), "+f"(d[3])
                 : "r"(a[0]), "r"(a[1]), "r"(a[2]), "r"(a[3]), "r"(b0), "r"(b1));
}
__device__ __forceinline__ uint32_t cvt2bf(float hi, float lo) {
    uint32_t r; asm("cvt.rn.bf16x2.f32 %0, %1, %2;" : "=r"(r) : "f"(hi), "f"(lo)); return r;
}
__device__ __forceinline__ float bflo(uint32_t p) { return __uint_as_float(p << 16); }
__device__ __forceinline__ float bfhi(uint32_t p) { return __uint_as_float(p & 0xffff0000u); }

__device__ __forceinline__ void cp_async16(uint32_t saddr, const void* gptr) {
    asm volatile("cp.async.cg.shared.global [%0], [%1], 16;" :: "r"(saddr), "l"(gptr));
}
#define CP_COMMIT()  asm volatile("cp.async.commit_group;" ::: "memory")
#define CP_WAIT(n)   asm volatile("cp.async.wait_group %0;" :: "n"(n) : "memory")

// ---- scratch (device globals: allocation-free rule) ----
__device__ float g_q[MROWS*DIM];
__device__ float g_k[MROWS*DIM];
__device__ __nv_bfloat16 x_h[MROWS*DIM],  x_l[MROWS*DIM];
__device__ __nv_bfloat16 wq_h[DIM*DIM], wq_l[DIM*DIM];
__device__ __nv_bfloat16 wk_h[DIM*DIM], wk_l[DIM*DIM];
__device__ __nv_bfloat16 wv_h[DIM*DIM], wv_l[DIM*DIM];
__device__ __nv_bfloat16 wo_h[DIM*DIM], wo_l[DIM*DIM];
__device__ __nv_bfloat16 q_h[MROWS*DIM], q_l[MROWS*DIM];
__device__ __nv_bfloat16 k_h[MROWS*DIM], k_l[MROWS*DIM];
__device__ __nv_bfloat16 v_h[MROWS*DIM], v_l[MROWS*DIM];
__device__ __nv_bfloat16 a_h[MROWS*DIM], a_l[MROWS*DIM];

__device__ __forceinline__ void split4(float4 v, uint2& hi, uint2& lo) {
    __nv_bfloat16 h0 = __float2bfloat16(v.x);
    __nv_bfloat16 h1 = __float2bfloat16(v.y);
    __nv_bfloat16 h2 = __float2bfloat16(v.z);
    __nv_bfloat16 h3 = __float2bfloat16(v.w);
    __nv_bfloat16 l0 = __float2bfloat16(v.x - __bfloat162float(h0));
    __nv_bfloat16 l1 = __float2bfloat16(v.y - __bfloat162float(h1));
    __nv_bfloat16 l2 = __float2bfloat16(v.z - __bfloat162float(h2));
    __nv_bfloat16 l3 = __float2bfloat16(v.w - __bfloat162float(h3));
    hi.x = ((uint32_t)__bfloat16_as_ushort(h1) << 16) | __bfloat16_as_ushort(h0);
    hi.y = ((uint32_t)__bfloat16_as_ushort(h3) << 16) | __bfloat16_as_ushort(h2);
    lo.x = ((uint32_t)__bfloat16_as_ushort(l1) << 16) | __bfloat16_as_ushort(l0);
    lo.y = ((uint32_t)__bfloat16_as_ushort(l3) << 16) | __bfloat16_as_ushort(l2);
}

// ============================================================================
// fp32 -> bf16 hi/lo split kernels
// ============================================================================
__global__ void __launch_bounds__(256) split_x_kernel(const float* __restrict__ src, int n4)
{
    const int i = blockIdx.x * blockDim.x + threadIdx.x;
    if (i >= n4) return;
    const float4 v = ((const float4*)src)[i];
    uint2 h, l; split4(v, h, l);
    ((uint2*)x_h)[i] = h;
    ((uint2*)x_l)[i] = l;
}

__global__ void __launch_bounds__(256) split_w_kernel(
    const float* __restrict__ wq, const float* __restrict__ wk,
    const float* __restrict__ wv, const float* __restrict__ wo, int n4)
{
    const int i = blockIdx.x * blockDim.x + threadIdx.x;
    if (i >= n4) return;
    const float* s;
    __nv_bfloat16 *hi, *lo;
    switch (blockIdx.y) {
        case 0: s = wq; hi = wq_h; lo = wq_l; break;
        case 1: s = wk; hi = wk_h; lo = wk_l; break;
        case 2: s = wv; hi = wv_h; lo = wv_l; break;
        default: s = wo; hi = wo_h; lo = wo_l; break;
    }
    const float4 v = ((const float4*)s)[i];
    uint2 h, l; split4(v, h, l);
    ((uint2*)hi)[i] = h;
    ((uint2*)lo)[i] = l;
}

// ============================================================================
// HMMA GEMM: C[M,N] = (Ah+Al)[M,K] @ (Bh+Bl)[N,K]^T + bias
// 128x128 CTA tile, 8 warps (2x4), 3 MMAs per product, fp32 accum.
// 2-stage cp.async pipeline; 2 CTAs/SM. BF16OUT writes hi/lo split directly.
// ============================================================================
#define BK        32
#define NSTAGES   (DIM / BK)            /* 64 */
#define LDS_B     40
#define TILE_BYT  (128 * LDS_B * 2)     /* 10240 */
#define OFF_AHI   0
#define OFF_ALO   (1 * TILE_BYT)
#define OFF_BHI   (2 * TILE_BYT)
#define OFF_BLO   (3 * TILE_BYT)
#define STG_BYT   (4 * TILE_BYT)        /* 40960 */
#define GEMM_SMEM (2 * STG_BYT)         /* 81920 -> 2 CTAs/SM */

__device__ __forceinline__ void gemm_issue(uint32_t dstbase,
    const __nv_bfloat16* __restrict__ Ah, const __nv_bfloat16* __restrict__ Al,
    const __nv_bfloat16* __restrict__ Bh, const __nv_bfloat16* __restrict__ Bl,
    int rowBase, int colBase, int kofs, int tid)
{
#pragma unroll
    for (int i = 0; i < 2; ++i) {
        const int f = i * 256 + tid;
        const int r = f >> 2, c = f & 3;
        const uint32_t d = dstbase + (uint32_t)r * (LDS_B * 2) + (uint32_t)c * 16;
        const size_t gA = (size_t)(rowBase + r) * DIM + kofs + c * 8;
        const size_t gB = (size_t)(colBase + r) * DIM + kofs + c * 8;
        cp_async16(d + OFF_AHI, Ah + gA);
        cp_async16(d + OFF_ALO, Al + gA);
        cp_async16(d + OFF_BHI, Bh + gB);
        cp_async16(d + OFF_BLO, Bl + gB);
    }
    CP_COMMIT();
}

template<bool BF16OUT>
__device__ __forceinline__ void gemm_tc_core(
    const __nv_bfloat16* __restrict__ Ah, const __nv_bfloat16* __restrict__ Al,
    const __nv_bfloat16* __restrict__ Bh, const __nv_bfloat16* __restrict__ Bl,
    const float* __restrict__ bias, float* __restrict__ C,
    __nv_bfloat16* __restrict__ Ch, __nv_bfloat16* __restrict__ Cl)
{
    extern __shared__ char smem[];
    const uint32_t smem_u = smem_to_u32(smem);
    const int tid  = threadIdx.x;
    const int lane = tid & 31;
    const int wid  = tid >> 5;
    const int wm   = wid & 1;
    const int wn   = wid >> 1;

    const int rowBase = blockIdx.y * 128;
    const int colBase = blockIdx.x * 128;

    const uint32_t a_off = (uint32_t)(wm * 64 + (lane & 15)) * (LDS_B * 2)
                         + (uint32_t)((lane >> 4) * 8) * 2;
    const uint32_t b_off = (uint32_t)(wn * 32 + ((lane >> 4) & 1) * 8 + (lane & 7)) * (LDS_B * 2)
                         + (uint32_t)(((lane >> 3) & 1) * 8) * 2;

    float acc[4][4][4];
#pragma unroll
    for (int t = 0; t < 4; ++t)
#pragma unroll
        for (int n = 0; n < 4; ++n)
#pragma unroll
            for (int e = 0; e < 4; ++e) acc[t][n][e] = 0.0f;

    gemm_issue(smem_u,           Ah, Al, Bh, Bl, rowBase, colBase, 0,  tid);
    gemm_issue(smem_u + STG_BYT, Ah, Al, Bh, Bl, rowBase, colBase, BK, tid);

    for (int s = 0; s < NSTAGES; ++s) {
        CP_WAIT(1);
        __syncthreads();

        const uint32_t cb = smem_u + (uint32_t)(s & 1) * STG_BYT;
#pragma unroll
        for (int ks = 0; ks < 2; ++ks) {
            uint32_t ah[4][4], al[4][4], bh[2][4], bl[2][4];
#pragma unroll
            for (int t = 0; t < 4; ++t) {
                ldsm4(ah[t], cb + OFF_AHI + a_off + (uint32_t)t * (16 * LDS_B * 2) + ks * 32);
                ldsm4(al[t], cb + OFF_ALO + a_off + (uint32_t)t * (16 * LDS_B * 2) + ks * 32);
            }
#pragma unroll
            for (int p = 0; p < 2; ++p) {
                ldsm4(bh[p], cb + OFF_BHI + b_off + (uint32_t)p * (16 * LDS_B * 2) + ks * 32);
                ldsm4(bl[p], cb + OFF_BLO + b_off + (uint32_t)p * (16 * LDS_B * 2) + ks * 32);
            }
#pragma unroll
            for (int t = 0; t < 4; ++t) {
#pragma unroll
                for (int n = 0; n < 4; ++n) {
                    const int p = n >> 1, sub = n & 1;
                    mma_bf16(acc[t][n], ah[t], bh[p][sub * 2], bh[p][sub * 2 + 1]);
                    mma_bf16(acc[t][n], ah[t], bl[p][sub * 2], bl[p][sub * 2 + 1]);
                    mma_bf16(acc[t][n], al[t], bh[p][sub * 2], bh[p][sub * 2 + 1]);
                }
            }
        }

        __syncthreads();
        if (s + 2 < NSTAGES)
            gemm_issue(smem_u + (uint32_t)(s & 1) * STG_BYT, Ah, Al, Bh, Bl,
                       rowBase, colBase, (s + 2) * BK, tid);
        else
            CP_COMMIT();
    }

#pragma unroll
    for (int t = 0; t < 4; ++t) {
        const int r1 = rowBase + wm * 64 + t * 16 + (lane >> 2);
#pragma unroll
        for (int n = 0; n < 4; ++n) {
            const int col = colBase + wn * 32 + n * 8 + (lane & 3) * 2;
            const float2 b2 = *(const float2*)&bias[col];
            const float o1x = acc[t][n][0] + b2.x, o1y = acc[t][n][1] + b2.y;
            const float o2x = acc[t][n][2] + b2.x, o2y = acc[t][n][3] + b2.y;
            if (!BF16OUT) {
                float2 o1, o2;
                o1.x = o1x; o1.y = o1y; o2.x = o2x; o2.y = o2y;
                *(float2*)&C[(size_t)r1 * DIM + col]       = o1;
                *(float2*)&C[(size_t)(r1 + 8) * DIM + col] = o2;
            } else {
                const uint32_t h1 = cvt2bf(o1y, o1x);
                const uint32_t l1 = cvt2bf(o1y - bfhi(h1), o1x - bflo(h1));
                const uint32_t h2 = cvt2bf(o2y, o2x);
                const uint32_t l2 = cvt2bf(o2y - bfhi(h2), o2x - bflo(h2));
                *(uint32_t*)&Ch[(size_t)r1 * DIM + col]       = h1;
                *(uint32_t*)&Cl[(size_t)r1 * DIM + col]       = l1;
                *(uint32_t*)&Ch[(size_t)(r1 + 8) * DIM + col] = h2;
                *(uint32_t*)&Cl[(size_t)(r1 + 8) * DIM + col] = l2;
            }
        }
    }
}

__global__ void __launch_bounds__(256, 2) gemm_qkv_kernel(
    const float* __restrict__ bq, const float* __restrict__ bk, const float* __restrict__ bv)
{
    if (blockIdx.z == 0)
        gemm_tc_core<false>(x_h, x_l, wq_h, wq_l, bq, g_q, nullptr, nullptr);
    else if (blockIdx.z == 1)
        gemm_tc_core<false>(x_h, x_l, wk_h, wk_l, bk, g_k, nullptr, nullptr);
    else
        gemm_tc_core<true>(x_h, x_l, wv_h, wv_l, bv, nullptr, v_h, v_l);
}

__global__ void __launch_bounds__(256, 2) gemm_out_kernel(
    const float* __restrict__ bo, float* __restrict__ out)
{
    gemm_tc_core<false>(a_h, a_l, wo_h, wo_l, bo, out, nullptr, nullptr);
}

// ============================================================================
// Fused RMSNorm(+gain) + RoPE. Reads g_q/g_k fp32, writes bf16 hi/lo pairs.
// ============================================================================
__global__ void __launch_bounds__(256) rmsnorm_rope_kernel(
    const float* __restrict__ freqs, const float* __restrict__ gq, const float* __restrict__ gk)
{
    const int row = blockIdx.x;
    const int s = row & (SEQ - 1);
    const float* xb = (blockIdx.y == 0 ? g_q : g_k) + (size_t)row * DIM;
    __nv_bfloat16* oh = (blockIdx.y == 0 ? q_h : k_h) + (size_t)row * DIM;
    __nv_bfloat16* ol = (blockIdx.y == 0 ? q_l : k_l) + (size_t)row * DIM;
    const float* g = (blockIdx.y == 0) ? gq : gk;
    const int tid = threadIdx.x;
    const int base = tid * 8;

    const float4 u = *(const float4*)(xb + base);
    const float4 w = *(const float4*)(xb + base + 4);
    float ss = u.x*u.x + u.y*u.y + u.z*u.z + u.w*u.w
             + w.x*w.x + w.y*w.y + w.z*w.z + w.w*w.w;
#pragma unroll
    for (int m = 16; m > 0; m >>= 1) ss += __shfl_xor_sync(0xffffffffu, ss, m);
    __shared__ float red[8];
    if ((tid & 31) == 0) red[tid >> 5] = ss;
    __syncthreads();
    const float tot = red[0]+red[1]+red[2]+red[3]+red[4]+red[5]+red[6]+red[7];
    const float rinv = rsqrtf(tot * (1.0f/DIM) + 1e-6f);

    const float4 g0 = *(const float4*)(g + base);
    const float4 g1 = *(const float4*)(g + base + 4);
    float y[8] = {u.x*rinv*g0.x, u.y*rinv*g0.y, u.z*rinv*g0.z, u.w*rinv*g0.w,
                  w.x*rinv*g1.x, w.y*rinv*g1.y, w.z*rinv*g1.z, w.w*rinv*g1.w};

    const float* fr = freqs + (size_t)s * HD;
    float o[8];
#pragma unroll
    for (int p = 0; p < 4; ++p) {
        const int col = base + 2*p;
        const int jj = (col & (HD - 1)) >> 1;
        const float cr = fr[2*jj], ci = fr[2*jj + 1];
        const float xr = y[2*p], xi = y[2*p + 1];
        o[2*p]     = xr*cr - xi*ci;
        o[2*p + 1] = xr*ci + xi*cr;
    }
    float4 r0; r0.x = o[0]; r0.y = o[1]; r0.z = o[2]; r0.w = o[3];
    float4 r1; r1.x = o[4]; r1.y = o[5]; r1.z = o[6]; r1.w = o[7];
    uint2 h, l;
    split4(r0, h, l);
    *(uint2*)(oh + base)     = h;
    *(uint2*)(ol + base)     = l;
    split4(r1, h, l);
    *(uint2*)(oh + base + 4) = h;
    *(uint2*)(ol + base + 4) = l;
}

// ============================================================================
// HMMA flash attention. 128 q-rows/CTA, 128-kv tiles.
// Q fragments live in registers (loaded straight from gmem, A-frag layout).
// Smem: K double-buffered (hi/lo) + V single (hi/lo) = 6 tiles.
// K_{i+1} load overlaps softmax+PV_i; V_i load overlaps QK_i.
// ============================================================================
#define AST   136                        /* halves per smem row */
#define ATILE_BYT (128 * AST * 2)        /* 34816 */
/* K buf0: [0,2T), K buf1: [2T,4T), V: [4T,6T)  (each pair = hi then lo) */
#define AVH  (4 * ATILE_BYT)
#define AVL  (5 * ATILE_BYT)
#define ATTN_SMEM (6 * ATILE_BYT)        /* 208896 */

__device__ __forceinline__ void attn_issue(uint32_t dstH, uint32_t dstL,
    const __nv_bfloat16* __restrict__ srcH, const __nv_bfloat16* __restrict__ srcL,
    size_t gbase, int tid)
{
#pragma unroll
    for (int i = 0; i < 8; ++i) {
        const int f = i * 256 + tid;
        const int r = f >> 4, c = f & 15;
        const uint32_t d = (uint32_t)r * (AST * 2) + (uint32_t)c * 16;
        const size_t gsrc = gbase + (size_t)r * DIM + c * 8;
        cp_async16(dstH + d, srcH + gsrc);
        cp_async16(dstL + d, srcL + gsrc);
    }
    CP_COMMIT();
}

__global__ void __launch_bounds__(256) attn_kernel()
{
    extern __shared__ char smh[];
    const uint32_t smem_u = smem_to_u32(smh);
    const int tid  = threadIdx.x;
    const int lane = tid & 31;
    const int w    = tid >> 5;
    const int b    = blockIdx.z;
    const int h    = blockIdx.y;
    const int q0   = blockIdx.x * 128;

    const size_t krow0 = (size_t)(b*SEQ) * DIM + h*HD;

    // ---- prologue: issue K tile 0 into K buf0 ----
    attn_issue(smem_u, smem_u + ATILE_BYT, k_h, k_l, krow0, tid);

    // ---- Q fragments -> registers (m16n8k16 A layout) ----
    // lane: row r = lane>>2 (and +8), k-pair col c0 = (lane&3)*2 (and +8)
    uint32_t qh[8][4], ql[8][4];
    {
        const size_t qbase = (size_t)(b*SEQ + q0 + w*16) * DIM + h*HD;
        const int r0 = lane >> 2;
        const int c0 = (lane & 3) * 2;
#pragma unroll
        for (int kc = 0; kc < 8; ++kc) {
            const size_t k0 = qbase + kc * 16 + c0;
            qh[kc][0] = *(const uint32_t*)&q_h[k0 + (size_t)r0 * DIM];
            qh[kc][1] = *(const uint32_t*)&q_h[k0 + (size_t)(r0 + 8) * DIM];
            qh[kc][2] = *(const uint32_t*)&q_h[k0 + 8 + (size_t)r0 * DIM];
            qh[kc][3] = *(const uint32_t*)&q_h[k0 + 8 + (size_t)(r0 + 8) * DIM];
            ql[kc][0] = *(const uint32_t*)&q_l[k0 + (size_t)r0 * DIM];
            ql[kc][1] = *(const uint32_t*)&q_l[k0 + (size_t)(r0 + 8) * DIM];
            ql[kc][2] = *(const uint32_t*)&q_l[k0 + 8 + (size_t)r0 * DIM];
            ql[kc][3] = *(const uint32_t*)&q_l[k0 + 8 + (size_t)(r0 + 8) * DIM];
        }
    }

    const uint32_t kb_off = ((uint32_t)(((lane >> 4) & 1) * 8 + (lane & 7)) * AST
                           + (uint32_t)(((lane >> 3) & 1) * 8)) * 2;
    const uint32_t vb_off = ((uint32_t)(((lane >> 3) & 1) * 8 + (lane & 7)) * AST
                           + (uint32_t)(((lane >> 4) & 1) * 8)) * 2;

    float O[16][4];
#pragma unroll
    for (int n = 0; n < 16; ++n)
#pragma unroll
        for (int e = 0; e < 4; ++e) O[n][e] = 0.0f;
    float mq0 = -1e30f, mq1 = -1e30f, l0 = 0.0f, l1 = 0.0f;

    const float Cs = 0.12754276931699657f;   // (1/sqrt(128)) * log2(e)

    for (int kt = 0; kt < SEQ / 128; ++kt) {
        const size_t krow = krow0 + (size_t)(kt * 128) * DIM;

        CP_WAIT(0);        // K_kt resident (V_{kt-1} completed earlier)
        __syncthreads();   // K visible to all; all warps past PV_{kt-1}

        // V_kt load overlaps QK
        attn_issue(smem_u + AVH, smem_u + AVL, v_h, v_l, krow, tid);

        // ---- scores over 128 kv cols (K from buffer kt&1) ----
        const uint32_t kbase = smem_u + (uint32_t)(kt & 1) * (2 * ATILE_BYT);
        float acc[16][4];
#pragma unroll
        for (int n = 0; n < 16; ++n)
#pragma unroll
            for (int e = 0; e < 4; ++e) acc[n][e] = 0.0f;

#pragma unroll
        for (int kc = 0; kc < 8; ++kc) {
#pragma unroll
            for (int np = 0; np < 8; ++np) {
                uint32_t kbh[4], kbl[4];
                ldsm4(kbh, kbase + kb_off + (uint32_t)np * (16 * AST * 2) + kc * 32);
                ldsm4(kbl, kbase + ATILE_BYT + kb_off + (uint32_t)np * (16 * AST * 2) + kc * 32);
                mma_bf16(acc[2*np],   qh[kc], kbh[0], kbh[1]);
                mma_bf16(acc[2*np],   qh[kc], kbl[0], kbl[1]);
                mma_bf16(acc[2*np],   ql[kc], kbh[0], kbh[1]);
                mma_bf16(acc[2*np+1], qh[kc], kbh[2], kbh[3]);
                mma_bf16(acc[2*np+1], qh[kc], kbl[2], kbl[3]);
                mma_bf16(acc[2*np+1], ql[kc], kbh[2], kbh[3]);
            }
        }

        // K_{kt+1} load overlaps softmax + PV (other K buffer; safe: all warps
        // past QK_{kt-1} via this iteration's top sync)
        if (kt + 1 < SEQ / 128) {
            attn_issue(smem_u + (uint32_t)((kt + 1) & 1) * (2 * ATILE_BYT),
                       smem_u + (uint32_t)((kt + 1) & 1) * (2 * ATILE_BYT) + ATILE_BYT,
                       k_h, k_l, krow + 128 * DIM, tid);
        } else {
            CP_COMMIT();
        }

        // ---- online softmax ----
        float pm0 = -1e30f, pm1 = -1e30f;
#pragma unroll
        for (int n = 0; n < 16; ++n) {
            pm0 = fmaxf(pm0, fmaxf(acc[n][0], acc[n][1]));
            pm1 = fmaxf(pm1, fmaxf(acc[n][2], acc[n][3]));
        }
        pm0 = fmaxf(pm0, __shfl_xor_sync(0xffffffffu, pm0, 1));
        pm0 = fmaxf(pm0, __shfl_xor_sync(0xffffffffu, pm0, 2));
        pm1 = fmaxf(pm1, __shfl_xor_sync(0xffffffffu, pm1, 1));
        pm1 = fmaxf(pm1, __shfl_xor_sync(0xffffffffu, pm1, 2));

        const float M0 = fmaxf(mq0, pm0 * Cs);
        const float M1 = fmaxf(mq1, pm1 * Cs);
        const float corr0 = exp2f(mq0 - M0);
        const float corr1 = exp2f(mq1 - M1);
        mq0 = M0; mq1 = M1;

        float rs0 = 0.0f, rs1 = 0.0f;
#pragma unroll
        for (int n = 0; n < 16; ++n) {
            acc[n][0] = exp2f(fmaf(acc[n][0], Cs, -M0));
            acc[n][1] = exp2f(fmaf(acc[n][1], Cs, -M0));
            acc[n][2] = exp2f(fmaf(acc[n][2], Cs, -M1));
            acc[n][3] = exp2f(fmaf(acc[n][3], Cs, -M1));
            rs0 += acc[n][0] + acc[n][1];
            rs1 += acc[n][2] + acc[n][3];
        }
        rs0 += __shfl_xor_sync(0xffffffffu, rs0, 1);
        rs0 += __shfl_xor_sync(0xffffffffu, rs0, 2);
        rs1 += __shfl_xor_sync(0xffffffffu, rs1, 1);
        rs1 += __shfl_xor_sync(0xffffffffu, rs1, 2);
        l0 = l0 * corr0 + rs0;
        l1 = l1 * corr1 + rs1;

#pragma unroll
        for (int n = 0; n < 16; ++n) {
            O[n][0] *= corr0; O[n][1] *= corr0;
            O[n][2] *= corr1; O[n][3] *= corr1;
        }

        CP_WAIT(1);        // V_kt resident (K_{kt+1} may still be in flight)
        __syncthreads();

        // ---- O += P @ V ----
#pragma unroll
        for (int kc = 0; kc < 8; ++kc) {
            uint32_t ph[4], pl[4];
            ph[0] = cvt2bf(acc[2*kc][1],   acc[2*kc][0]);
            ph[1] = cvt2bf(acc[2*kc][3],   acc[2*kc][2]);
            ph[2] = cvt2bf(acc[2*kc+1][1], acc[2*kc+1][0]);
            ph[3] = cvt2bf(acc[2*kc+1][3], acc[2*kc+1][2]);
            {
                float e0 = acc[2*kc][0]   - bflo(ph[0]);
                float e1 = acc[2*kc][1]   - bfhi(ph[0]);
                pl[0] = cvt2bf(e1, e0);
                e0 = acc[2*kc][2]   - bflo(ph[1]);
                e1 = acc[2*kc][3]   - bfhi(ph[1]);
                pl[1] = cvt2bf(e1, e0);
                e0 = acc[2*kc+1][0] - bflo(ph[2]);
                e1 = acc[2*kc+1][1] - bfhi(ph[2]);
                pl[2] = cvt2bf(e1, e0);
                e0 = acc[2*kc+1][2] - bflo(ph[3]);
                e1 = acc[2*kc+1][3] - bfhi(ph[3]);
                pl[3] = cvt2bf(e1, e0);
            }
#pragma unroll
            for (int np = 0; np < 8; ++np) {
                uint32_t vbh[4], vbl[4];
                ldsm4t(vbh, smem_u + AVH + vb_off + (uint32_t)kc * (16 * AST * 2) + np * 32);
                ldsm4t(vbl, smem_u + AVL + vb_off + (uint32_t)kc * (16 * AST * 2) + np * 32);
                mma_bf16(O[2*np],   ph, vbh[0], vbh[1]);
                mma_bf16(O[2*np],   ph, vbl[0], vbl[1]);
                mma_bf16(O[2*np],   pl, vbh[0], vbh[1]);
                mma_bf16(O[2*np+1], ph, vbh[2], vbh[3]);
                mma_bf16(O[2*np+1], ph, vbl[2], vbl[3]);
                mma_bf16(O[2*np+1], pl, vbh[2], vbh[3]);
            }
        }
    }

    // ---- finalize: write bf16 hi/lo output ----
    const float inv0 = 1.0f / l0;
    const float inv1 = 1.0f / l1;
    const size_t r0g = (size_t)(b*SEQ + q0 + w*16 + (lane >> 2));
#pragma unroll
    for (int n = 0; n < 16; ++n) {
        const int col = h*HD + 8*n + 2*(lane & 3);
        const float o1x = O[n][0] * inv0, o1y = O[n][1] * inv0;
        const float o2x = O[n][2] * inv1, o2y = O[n][3] * inv1;
        const uint32_t h1 = cvt2bf(o1y, o1x);
        const uint32_t l1p = cvt2bf(o1y - bfhi(h1), o1x - bflo(h1));
        const uint32_t h2 = cvt2bf(o2y, o2x);
        const uint32_t l2p = cvt2bf(o2y - bfhi(h2), o2x - bflo(h2));
        *(uint32_t*)&a_h[r0g * DIM + col]       = h1;
        *(uint32_t*)&a_l[r0g * DIM + col]       = l1p;
        *(uint32_t*)&a_h[(r0g + 8) * DIM + col] = h2;
        *(uint32_t*)&a_l[(r0g + 8) * DIM + col] = l2p;
    }
}

// ============================================================================
// Launcher
// ============================================================================
extern "C" void kernel_launch(void* const* d_in, const int* in_sizes, int n_in,
                              void* d_out, int out_size)
{
    const float* x  = (const float*)d_in[0];
    const float* fr = (const float*)d_in[1];
    const float* wq = (const float*)d_in[2];
    const float* bq = (const float*)d_in[3];
    const float* wk = (const float*)d_in[4];
    const float* bk = (const float*)d_in[5];
    const float* wv = (const float*)d_in[6];
    const float* bv = (const float*)d_in[7];
    const float* wo = (const float*)d_in[8];
    const float* bo = (const float*)d_in[9];
    const float* gq = (const float*)d_in[10];
    const float* gk = (const float*)d_in[11];
    float* out = (float*)d_out;

    (void)in_sizes; (void)n_in; (void)out_size;

    cudaFuncSetAttribute(gemm_qkv_kernel, cudaFuncAttributeMaxDynamicSharedMemorySize, GEMM_SMEM);
    cudaFuncSetAttribute(gemm_out_kernel, cudaFuncAttributeMaxDynamicSharedMemorySize, GEMM_SMEM);
    cudaFuncSetAttribute(attn_kernel, cudaFuncAttributeMaxDynamicSharedMemorySize, ATTN_SMEM);

    const int n4_x = MROWS * DIM / 4;
    const int n4_w = DIM * DIM / 4;

    split_x_kernel<<<n4_x / 256, 256>>>(x, n4_x);
    split_w_kernel<<<dim3(n4_w / 256, 4), 256>>>(wq, wk, wv, wo, n4_w);

    gemm_qkv_kernel<<<dim3(DIM/128, MROWS/128, 3), 256, GEMM_SMEM>>>(bq, bk, bv);

    rmsnorm_rope_kernel<<<dim3(MROWS, 2), 256>>>(fr, gq, gk);

    attn_kernel<<<dim3(SEQ/128, NH, BSZ), 256, ATTN_SMEM>>>();

    gemm_out_kernel<<<dim3(DIM/128, MROWS/128, 1), 256, GEMM_SMEM>>>(bo, out);
}

// round 15
// speedup vs baseline: 1.0014x; 1.0014x over previous
#include <cuda_runtime.h>
#include <cuda_bf16.h>
#include <cstdint>

#define DIM   2048
#define BSZ   2
#define SEQ   2048
#define NH    16
#define HD    128
#define MROWS (BSZ*SEQ)   /* 4096 */

typedef unsigned long long ull;

// ---- PTX helpers (baseline PTX only; no sm_103a-gated features) ----
__device__ __forceinline__ uint32_t smem_to_u32(const void* p) {
    uint32_t a;
    asm("{ .reg .u64 t; cvta.to.shared.u64 t, %1; cvt.u32.u64 %0, t; }" : "=r"(a) : "l"(p));
    return a;
}
__device__ __forceinline__ void ldsm4(uint32_t (&r)[4], uint32_t addr) {
    asm volatile("ldmatrix.sync.aligned.m8n8.x4.shared.b16 {%0,%1,%2,%3}, [%4];"
                 : "=r"(r[0]), "=r"(r[1]), "=r"(r[2]), "=r"(r[3]) : "r"(addr));
}
__device__ __forceinline__ void ldsm4t(uint32_t (&r)[4], uint32_t addr) {
    asm volatile("ldmatrix.sync.aligned.m8n8.x4.trans.shared.b16 {%0,%1,%2,%3}, [%4];"
                 : "=r"(r[0]), "=r"(r[1]), "=r"(r[2]), "=r"(r[3]) : "r"(addr));
}
__device__ __forceinline__ void mma_bf16(float (&d)[4], const uint32_t (&a)[4],
                                         uint32_t b0, uint32_t b1) {
    asm volatile("mma.sync.aligned.m16n8k16.row.col.f32.bf16.bf16.f32 "
                 "{%0,%1,%2,%3}, {%4,%5,%6,%7}, {%8,%9}, {%0,%1,%2,%3};"
                 : "+f"(d[0]), "+f"(d[1]), "+f"(d[2]), "+f"(d[3])
                 : "r"(a[0]), "r"(a[1]), "r"(a[2]), "r"(a[3]), "r"(b0), "r"(b1));
}
__device__ __forceinline__ uint32_t cvt2bf(float hi, float lo) {
    uint32_t r; asm("cvt.rn.bf16x2.f32 %0, %1, %2;" : "=r"(r) : "f"(hi), "f"(lo)); return r;
}
__device__ __forceinline__ float bflo(uint32_t p) { return __uint_as_float(p << 16); }
__device__ __forceinline__ float bfhi(uint32_t p) { return __uint_as_float(p & 0xffff0000u); }

__device__ __forceinline__ void cp_async16(uint32_t saddr, const void* gptr) {
    asm volatile("cp.async.cg.shared.global [%0], [%1], 16;" :: "r"(saddr), "l"(gptr));
}
#define CP_COMMIT()  asm volatile("cp.async.commit_group;" ::: "memory")
#define CP_WAIT(n)   asm volatile("cp.async.wait_group %0;" :: "n"(n) : "memory")

// ---- scratch (device globals: allocation-free rule) ----
__device__ float g_q[MROWS*DIM];
__device__ float g_k[MROWS*DIM];
__device__ __nv_bfloat16 x_h[MROWS*DIM],  x_l[MROWS*DIM];
__device__ __nv_bfloat16 wq_h[DIM*DIM], wq_l[DIM*DIM];
__device__ __nv_bfloat16 wk_h[DIM*DIM], wk_l[DIM*DIM];
__device__ __nv_bfloat16 wv_h[DIM*DIM], wv_l[DIM*DIM];
__device__ __nv_bfloat16 wo_h[DIM*DIM], wo_l[DIM*DIM];
__device__ __nv_bfloat16 q_h[MROWS*DIM], q_l[MROWS*DIM];
__device__ __nv_bfloat16 k_h[MROWS*DIM], k_l[MROWS*DIM];
__device__ __nv_bfloat16 v_h[MROWS*DIM], v_l[MROWS*DIM];
__device__ __nv_bfloat16 a_h[MROWS*DIM], a_l[MROWS*DIM];

__device__ __forceinline__ void split4(float4 v, uint2& hi, uint2& lo) {
    __nv_bfloat16 h0 = __float2bfloat16(v.x);
    __nv_bfloat16 h1 = __float2bfloat16(v.y);
    __nv_bfloat16 h2 = __float2bfloat16(v.z);
    __nv_bfloat16 h3 = __float2bfloat16(v.w);
    __nv_bfloat16 l0 = __float2bfloat16(v.x - __bfloat162float(h0));
    __nv_bfloat16 l1 = __float2bfloat16(v.y - __bfloat162float(h1));
    __nv_bfloat16 l2 = __float2bfloat16(v.z - __bfloat162float(h2));
    __nv_bfloat16 l3 = __float2bfloat16(v.w - __bfloat162float(h3));
    hi.x = ((uint32_t)__bfloat16_as_ushort(h1) << 16) | __bfloat16_as_ushort(h0);
    hi.y = ((uint32_t)__bfloat16_as_ushort(h3) << 16) | __bfloat16_as_ushort(h2);
    lo.x = ((uint32_t)__bfloat16_as_ushort(l1) << 16) | __bfloat16_as_ushort(l0);
    lo.y = ((uint32_t)__bfloat16_as_ushort(l3) << 16) | __bfloat16_as_ushort(l2);
}

// ============================================================================
// fp32 -> bf16 hi/lo split kernels
// ============================================================================
__global__ void __launch_bounds__(256) split_x_kernel(const float* __restrict__ src, int n4)
{
    const int i = blockIdx.x * blockDim.x + threadIdx.x;
    if (i >= n4) return;
    const float4 v = ((const float4*)src)[i];
    uint2 h, l; split4(v, h, l);
    ((uint2*)x_h)[i] = h;
    ((uint2*)x_l)[i] = l;
}

__global__ void __launch_bounds__(256) split_w_kernel(
    const float* __restrict__ wq, const float* __restrict__ wk,
    const float* __restrict__ wv, const float* __restrict__ wo, int n4)
{
    const int i = blockIdx.x * blockDim.x + threadIdx.x;
    if (i >= n4) return;
    const float* s;
    __nv_bfloat16 *hi, *lo;
    switch (blockIdx.y) {
        case 0: s = wq; hi = wq_h; lo = wq_l; break;
        case 1: s = wk; hi = wk_h; lo = wk_l; break;
        case 2: s = wv; hi = wv_h; lo = wv_l; break;
        default: s = wo; hi = wo_h; lo = wo_l; break;
    }
    const float4 v = ((const float4*)s)[i];
    uint2 h, l; split4(v, h, l);
    ((uint2*)hi)[i] = h;
    ((uint2*)lo)[i] = l;
}

// ============================================================================
// HMMA GEMM: C[M,N] = (Ah+Al)[M,K] @ (Bh+Bl)[N,K]^T + bias
// 128x128 CTA tile, 8 warps (2x4), 3 MMAs per product, fp32 accum.
// 2-stage cp.async pipeline; 2 CTAs/SM. BF16OUT writes hi/lo split directly.
// ============================================================================
#define BK        32
#define NSTAGES   (DIM / BK)            /* 64 */
#define LDS_B     40
#define TILE_BYT  (128 * LDS_B * 2)     /* 10240 */
#define OFF_AHI   0
#define OFF_ALO   (1 * TILE_BYT)
#define OFF_BHI   (2 * TILE_BYT)
#define OFF_BLO   (3 * TILE_BYT)
#define STG_BYT   (4 * TILE_BYT)        /* 40960 */
#define GEMM_SMEM (2 * STG_BYT)         /* 81920 -> 2 CTAs/SM */

__device__ __forceinline__ void gemm_issue(uint32_t dstbase,
    const __nv_bfloat16* __restrict__ Ah, const __nv_bfloat16* __restrict__ Al,
    const __nv_bfloat16* __restrict__ Bh, const __nv_bfloat16* __restrict__ Bl,
    int rowBase, int colBase, int kofs, int tid)
{
#pragma unroll
    for (int i = 0; i < 2; ++i) {
        const int f = i * 256 + tid;
        const int r = f >> 2, c = f & 3;
        const uint32_t d = dstbase + (uint32_t)r * (LDS_B * 2) + (uint32_t)c * 16;
        const size_t gA = (size_t)(rowBase + r) * DIM + kofs + c * 8;
        const size_t gB = (size_t)(colBase + r) * DIM + kofs + c * 8;
        cp_async16(d + OFF_AHI, Ah + gA);
        cp_async16(d + OFF_ALO, Al + gA);
        cp_async16(d + OFF_BHI, Bh + gB);
        cp_async16(d + OFF_BLO, Bl + gB);
    }
    CP_COMMIT();
}

template<bool BF16OUT>
__device__ __forceinline__ void gemm_tc_core(
    const __nv_bfloat16* __restrict__ Ah, const __nv_bfloat16* __restrict__ Al,
    const __nv_bfloat16* __restrict__ Bh, const __nv_bfloat16* __restrict__ Bl,
    const float* __restrict__ bias, float* __restrict__ C,
    __nv_bfloat16* __restrict__ Ch, __nv_bfloat16* __restrict__ Cl)
{
    extern __shared__ char smem[];
    const uint32_t smem_u = smem_to_u32(smem);
    const int tid  = threadIdx.x;
    const int lane = tid & 31;
    const int wid  = tid >> 5;
    const int wm   = wid & 1;
    const int wn   = wid >> 1;

    const int rowBase = blockIdx.y * 128;
    const int colBase = blockIdx.x * 128;

    const uint32_t a_off = (uint32_t)(wm * 64 + (lane & 15)) * (LDS_B * 2)
                         + (uint32_t)((lane >> 4) * 8) * 2;
    const uint32_t b_off = (uint32_t)(wn * 32 + ((lane >> 4) & 1) * 8 + (lane & 7)) * (LDS_B * 2)
                         + (uint32_t)(((lane >> 3) & 1) * 8) * 2;

    float acc[4][4][4];
#pragma unroll
    for (int t = 0; t < 4; ++t)
#pragma unroll
        for (int n = 0; n < 4; ++n)
#pragma unroll
            for (int e = 0; e < 4; ++e) acc[t][n][e] = 0.0f;

    gemm_issue(smem_u,           Ah, Al, Bh, Bl, rowBase, colBase, 0,  tid);
    gemm_issue(smem_u + STG_BYT, Ah, Al, Bh, Bl, rowBase, colBase, BK, tid);

    for (int s = 0; s < NSTAGES; ++s) {
        CP_WAIT(1);
        __syncthreads();

        const uint32_t cb = smem_u + (uint32_t)(s & 1) * STG_BYT;
#pragma unroll
        for (int ks = 0; ks < 2; ++ks) {
            uint32_t ah[4][4], al[4][4], bh[2][4], bl[2][4];
#pragma unroll
            for (int t = 0; t < 4; ++t) {
                ldsm4(ah[t], cb + OFF_AHI + a_off + (uint32_t)t * (16 * LDS_B * 2) + ks * 32);
                ldsm4(al[t], cb + OFF_ALO + a_off + (uint32_t)t * (16 * LDS_B * 2) + ks * 32);
            }
#pragma unroll
            for (int p = 0; p < 2; ++p) {
                ldsm4(bh[p], cb + OFF_BHI + b_off + (uint32_t)p * (16 * LDS_B * 2) + ks * 32);
                ldsm4(bl[p], cb + OFF_BLO + b_off + (uint32_t)p * (16 * LDS_B * 2) + ks * 32);
            }
#pragma unroll
            for (int t = 0; t < 4; ++t) {
#pragma unroll
                for (int n = 0; n < 4; ++n) {
                    const int p = n >> 1, sub = n & 1;
                    mma_bf16(acc[t][n], ah[t], bh[p][sub * 2], bh[p][sub * 2 + 1]);
                    mma_bf16(acc[t][n], ah[t], bl[p][sub * 2], bl[p][sub * 2 + 1]);
                    mma_bf16(acc[t][n], al[t], bh[p][sub * 2], bh[p][sub * 2 + 1]);
                }
            }
        }

        __syncthreads();
        if (s + 2 < NSTAGES)
            gemm_issue(smem_u + (uint32_t)(s & 1) * STG_BYT, Ah, Al, Bh, Bl,
                       rowBase, colBase, (s + 2) * BK, tid);
        else
            CP_COMMIT();
    }

#pragma unroll
    for (int t = 0; t < 4; ++t) {
        const int r1 = rowBase + wm * 64 + t * 16 + (lane >> 2);
#pragma unroll
        for (int n = 0; n < 4; ++n) {
            const int col = colBase + wn * 32 + n * 8 + (lane & 3) * 2;
            const float2 b2 = *(const float2*)&bias[col];
            const float o1x = acc[t][n][0] + b2.x, o1y = acc[t][n][1] + b2.y;
            const float o2x = acc[t][n][2] + b2.x, o2y = acc[t][n][3] + b2.y;
            if (!BF16OUT) {
                float2 o1, o2;
                o1.x = o1x; o1.y = o1y; o2.x = o2x; o2.y = o2y;
                *(float2*)&C[(size_t)r1 * DIM + col]       = o1;
                *(float2*)&C[(size_t)(r1 + 8) * DIM + col] = o2;
            } else {
                const uint32_t h1 = cvt2bf(o1y, o1x);
                const uint32_t l1 = cvt2bf(o1y - bfhi(h1), o1x - bflo(h1));
                const uint32_t h2 = cvt2bf(o2y, o2x);
                const uint32_t l2 = cvt2bf(o2y - bfhi(h2), o2x - bflo(h2));
                *(uint32_t*)&Ch[(size_t)r1 * DIM + col]       = h1;
                *(uint32_t*)&Cl[(size_t)r1 * DIM + col]       = l1;
                *(uint32_t*)&Ch[(size_t)(r1 + 8) * DIM + col] = h2;
                *(uint32_t*)&Cl[(size_t)(r1 + 8) * DIM + col] = l2;
            }
        }
    }
}

__global__ void __launch_bounds__(256, 2) gemm_qkv_kernel(
    const float* __restrict__ bq, const float* __restrict__ bk, const float* __restrict__ bv)
{
    if (blockIdx.z == 0)
        gemm_tc_core<false>(x_h, x_l, wq_h, wq_l, bq, g_q, nullptr, nullptr);
    else if (blockIdx.z == 1)
        gemm_tc_core<false>(x_h, x_l, wk_h, wk_l, bk, g_k, nullptr, nullptr);
    else
        gemm_tc_core<true>(x_h, x_l, wv_h, wv_l, bv, nullptr, v_h, v_l);
}

__global__ void __launch_bounds__(256, 2) gemm_out_kernel(
    const float* __restrict__ bo, float* __restrict__ out)
{
    gemm_tc_core<false>(a_h, a_l, wo_h, wo_l, bo, out, nullptr, nullptr);
}

// ============================================================================
// Fused RMSNorm(+gain) + RoPE. Reads g_q/g_k fp32, writes bf16 hi/lo pairs.
// ============================================================================
__global__ void __launch_bounds__(256) rmsnorm_rope_kernel(
    const float* __restrict__ freqs, const float* __restrict__ gq, const float* __restrict__ gk)
{
    const int row = blockIdx.x;
    const int s = row & (SEQ - 1);
    const float* xb = (blockIdx.y == 0 ? g_q : g_k) + (size_t)row * DIM;
    __nv_bfloat16* oh = (blockIdx.y == 0 ? q_h : k_h) + (size_t)row * DIM;
    __nv_bfloat16* ol = (blockIdx.y == 0 ? q_l : k_l) + (size_t)row * DIM;
    const float* g = (blockIdx.y == 0) ? gq : gk;
    const int tid = threadIdx.x;
    const int base = tid * 8;

    const float4 u = *(const float4*)(xb + base);
    const float4 w = *(const float4*)(xb + base + 4);
    float ss = u.x*u.x + u.y*u.y + u.z*u.z + u.w*u.w
             + w.x*w.x + w.y*w.y + w.z*w.z + w.w*w.w;
#pragma unroll
    for (int m = 16; m > 0; m >>= 1) ss += __shfl_xor_sync(0xffffffffu, ss, m);
    __shared__ float red[8];
    if ((tid & 31) == 0) red[tid >> 5] = ss;
    __syncthreads();
    const float tot = red[0]+red[1]+red[2]+red[3]+red[4]+red[5]+red[6]+red[7];
    const float rinv = rsqrtf(tot * (1.0f/DIM) + 1e-6f);

    const float4 g0 = *(const float4*)(g + base);
    const float4 g1 = *(const float4*)(g + base + 4);
    float y[8] = {u.x*rinv*g0.x, u.y*rinv*g0.y, u.z*rinv*g0.z, u.w*rinv*g0.w,
                  w.x*rinv*g1.x, w.y*rinv*g1.y, w.z*rinv*g1.z, w.w*rinv*g1.w};

    const float* fr = freqs + (size_t)s * HD;
    float o[8];
#pragma unroll
    for (int p = 0; p < 4; ++p) {
        const int col = base + 2*p;
        const int jj = (col & (HD - 1)) >> 1;
        const float cr = fr[2*jj], ci = fr[2*jj + 1];
        const float xr = y[2*p], xi = y[2*p + 1];
        o[2*p]     = xr*cr - xi*ci;
        o[2*p + 1] = xr*ci + xi*cr;
    }
    float4 r0; r0.x = o[0]; r0.y = o[1]; r0.z = o[2]; r0.w = o[3];
    float4 r1; r1.x = o[4]; r1.y = o[5]; r1.z = o[6]; r1.w = o[7];
    uint2 h, l;
    split4(r0, h, l);
    *(uint2*)(oh + base)     = h;
    *(uint2*)(ol + base)     = l;
    split4(r1, h, l);
    *(uint2*)(oh + base + 4) = h;
    *(uint2*)(ol + base + 4) = l;
}

// ============================================================================
// HMMA flash attention. 128 q-rows/CTA, 128-kv tiles.
// Q fragments live in registers (loaded straight from gmem, A-frag layout).
// Smem: K double-buffered (hi/lo) + V single (hi/lo) = 6 tiles.
// K_{i+1} load overlaps softmax+PV_i; V_i load overlaps QK_i.
// ============================================================================
#define AST   136                        /* halves per smem row */
#define ATILE_BYT (128 * AST * 2)        /* 34816 */
/* K buf0: [0,2T), K buf1: [2T,4T), V: [4T,6T)  (each pair = hi then lo) */
#define AVH  (4 * ATILE_BYT)
#define AVL  (5 * ATILE_BYT)
#define ATTN_SMEM (6 * ATILE_BYT)        /* 208896 */

__device__ __forceinline__ void attn_issue(uint32_t dstH, uint32_t dstL,
    const __nv_bfloat16* __restrict__ srcH, const __nv_bfloat16* __restrict__ srcL,
    size_t gbase, int tid)
{
#pragma unroll
    for (int i = 0; i < 8; ++i) {
        const int f = i * 256 + tid;
        const int r = f >> 4, c = f & 15;
        const uint32_t d = (uint32_t)r * (AST * 2) + (uint32_t)c * 16;
        const size_t gsrc = gbase + (size_t)r * DIM + c * 8;
        cp_async16(dstH + d, srcH + gsrc);
        cp_async16(dstL + d, srcL + gsrc);
    }
    CP_COMMIT();
}

__global__ void __launch_bounds__(256) attn_kernel()
{
    extern __shared__ char smh[];
    const uint32_t smem_u = smem_to_u32(smh);
    const int tid  = threadIdx.x;
    const int lane = tid & 31;
    const int w    = tid >> 5;
    const int b    = blockIdx.z;
    const int h    = blockIdx.y;
    const int q0   = blockIdx.x * 128;

    const size_t krow0 = (size_t)(b*SEQ) * DIM + h*HD;

    // ---- prologue: issue K tile 0 into K buf0 ----
    attn_issue(smem_u, smem_u + ATILE_BYT, k_h, k_l, krow0, tid);

    // ---- Q fragments -> registers (m16n8k16 A layout) ----
    // lane: row r = lane>>2 (and +8), k-pair col c0 = (lane&3)*2 (and +8)
    uint32_t qh[8][4], ql[8][4];
    {
        const size_t qbase = (size_t)(b*SEQ + q0 + w*16) * DIM + h*HD;
        const int r0 = lane >> 2;
        const int c0 = (lane & 3) * 2;
#pragma unroll
        for (int kc = 0; kc < 8; ++kc) {
            const size_t k0 = qbase + kc * 16 + c0;
            qh[kc][0] = *(const uint32_t*)&q_h[k0 + (size_t)r0 * DIM];
            qh[kc][1] = *(const uint32_t*)&q_h[k0 + (size_t)(r0 + 8) * DIM];
            qh[kc][2] = *(const uint32_t*)&q_h[k0 + 8 + (size_t)r0 * DIM];
            qh[kc][3] = *(const uint32_t*)&q_h[k0 + 8 + (size_t)(r0 + 8) * DIM];
            ql[kc][0] = *(const uint32_t*)&q_l[k0 + (size_t)r0 * DIM];
            ql[kc][1] = *(const uint32_t*)&q_l[k0 + (size_t)(r0 + 8) * DIM];
            ql[kc][2] = *(const uint32_t*)&q_l[k0 + 8 + (size_t)r0 * DIM];
            ql[kc][3] = *(const uint32_t*)&q_l[k0 + 8 + (size_t)(r0 + 8) * DIM];
        }
    }

    const uint32_t kb_off = ((uint32_t)(((lane >> 4) & 1) * 8 + (lane & 7)) * AST
                           + (uint32_t)(((lane >> 3) & 1) * 8)) * 2;
    const uint32_t vb_off = ((uint32_t)(((lane >> 3) & 1) * 8 + (lane & 7)) * AST
                           + (uint32_t)(((lane >> 4) & 1) * 8)) * 2;

    float O[16][4];
#pragma unroll
    for (int n = 0; n < 16; ++n)
#pragma unroll
        for (int e = 0; e < 4; ++e) O[n][e] = 0.0f;
    float mq0 = -1e30f, mq1 = -1e30f, l0 = 0.0f, l1 = 0.0f;

    const float Cs = 0.12754276931699657f;   // (1/sqrt(128)) * log2(e)

    for (int kt = 0; kt < SEQ / 128; ++kt) {
        const size_t krow = krow0 + (size_t)(kt * 128) * DIM;

        CP_WAIT(0);        // K_kt resident (V_{kt-1} completed earlier)
        __syncthreads();   // K visible to all; all warps past PV_{kt-1}

        // V_kt load overlaps QK
        attn_issue(smem_u + AVH, smem_u + AVL, v_h, v_l, krow, tid);

        // ---- scores over 128 kv cols (K from buffer kt&1) ----
        const uint32_t kbase = smem_u + (uint32_t)(kt & 1) * (2 * ATILE_BYT);
        float acc[16][4];
#pragma unroll
        for (int n = 0; n < 16; ++n)
#pragma unroll
            for (int e = 0; e < 4; ++e) acc[n][e] = 0.0f;

#pragma unroll
        for (int kc = 0; kc < 8; ++kc) {
#pragma unroll
            for (int np = 0; np < 8; ++np) {
                uint32_t kbh[4], kbl[4];
                ldsm4(kbh, kbase + kb_off + (uint32_t)np * (16 * AST * 2) + kc * 32);
                ldsm4(kbl, kbase + ATILE_BYT + kb_off + (uint32_t)np * (16 * AST * 2) + kc * 32);
                mma_bf16(acc[2*np],   qh[kc], kbh[0], kbh[1]);
                mma_bf16(acc[2*np],   qh[kc], kbl[0], kbl[1]);
                mma_bf16(acc[2*np],   ql[kc], kbh[0], kbh[1]);
                mma_bf16(acc[2*np+1], qh[kc], kbh[2], kbh[3]);
                mma_bf16(acc[2*np+1], qh[kc], kbl[2], kbl[3]);
                mma_bf16(acc[2*np+1], ql[kc], kbh[2], kbh[3]);
            }
        }

        // K_{kt+1} load overlaps softmax + PV (other K buffer; safe: all warps
        // past QK_{kt-1} via this iteration's top sync)
        if (kt + 1 < SEQ / 128) {
            attn_issue(smem_u + (uint32_t)((kt + 1) & 1) * (2 * ATILE_BYT),
                       smem_u + (uint32_t)((kt + 1) & 1) * (2 * ATILE_BYT) + ATILE_BYT,
                       k_h, k_l, krow + 128 * DIM, tid);
        } else {
            CP_COMMIT();
        }

        // ---- online softmax ----
        float pm0 = -1e30f, pm1 = -1e30f;
#pragma unroll
        for (int n = 0; n < 16; ++n) {
            pm0 = fmaxf(pm0, fmaxf(acc[n][0], acc[n][1]));
            pm1 = fmaxf(pm1, fmaxf(acc[n][2], acc[n][3]));
        }
        pm0 = fmaxf(pm0, __shfl_xor_sync(0xffffffffu, pm0, 1));
        pm0 = fmaxf(pm0, __shfl_xor_sync(0xffffffffu, pm0, 2));
        pm1 = fmaxf(pm1, __shfl_xor_sync(0xffffffffu, pm1, 1));
        pm1 = fmaxf(pm1, __shfl_xor_sync(0xffffffffu, pm1, 2));

        const float M0 = fmaxf(mq0, pm0 * Cs);
        const float M1 = fmaxf(mq1, pm1 * Cs);
        const float corr0 = exp2f(mq0 - M0);
        const float corr1 = exp2f(mq1 - M1);
        mq0 = M0; mq1 = M1;

        float rs0 = 0.0f, rs1 = 0.0f;
#pragma unroll
        for (int n = 0; n < 16; ++n) {
            acc[n][0] = exp2f(fmaf(acc[n][0], Cs, -M0));
            acc[n][1] = exp2f(fmaf(acc[n][1], Cs, -M0));
            acc[n][2] = exp2f(fmaf(acc[n][2], Cs, -M1));
            acc[n][3] = exp2f(fmaf(acc[n][3], Cs, -M1));
            rs0 += acc[n][0] + acc[n][1];
            rs1 += acc[n][2] + acc[n][3];
        }
        rs0 += __shfl_xor_sync(0xffffffffu, rs0, 1);
        rs0 += __shfl_xor_sync(0xffffffffu, rs0, 2);
        rs1 += __shfl_xor_sync(0xffffffffu, rs1, 1);
        rs1 += __shfl_xor_sync(0xffffffffu, rs1, 2);
        l0 = l0 * corr0 + rs0;
        l1 = l1 * corr1 + rs1;

#pragma unroll
        for (int n = 0; n < 16; ++n) {
            O[n][0] *= corr0; O[n][1] *= corr0;
            O[n][2] *= corr1; O[n][3] *= corr1;
        }

        CP_WAIT(1);        // V_kt resident (K_{kt+1} may still be in flight)
        __syncthreads();

        // ---- O += P @ V ----
#pragma unroll
        for (int kc = 0; kc < 8; ++kc) {
            uint32_t ph[4], pl[4];
            ph[0] = cvt2bf(acc[2*kc][1],   acc[2*kc][0]);
            ph[1] = cvt2bf(acc[2*kc][3],   acc[2*kc][2]);
            ph[2] = cvt2bf(acc[2*kc+1][1], acc[2*kc+1][0]);
            ph[3] = cvt2bf(acc[2*kc+1][3], acc[2*kc+1][2]);
            {
                float e0 = acc[2*kc][0]   - bflo(ph[0]);
                float e1 = acc[2*kc][1]   - bfhi(ph[0]);
                pl[0] = cvt2bf(e1, e0);
                e0 = acc[2*kc][2]   - bflo(ph[1]);
                e1 = acc[2*kc][3]   - bfhi(ph[1]);
                pl[1] = cvt2bf(e1, e0);
                e0 = acc[2*kc+1][0] - bflo(ph[2]);
                e1 = acc[2*kc+1][1] - bfhi(ph[2]);
                pl[2] = cvt2bf(e1, e0);
                e0 = acc[2*kc+1][2] - bflo(ph[3]);
                e1 = acc[2*kc+1][3] - bfhi(ph[3]);
                pl[3] = cvt2bf(e1, e0);
            }
#pragma unroll
            for (int np = 0; np < 8; ++np) {
                uint32_t vbh[4], vbl[4];
                ldsm4t(vbh, smem_u + AVH + vb_off + (uint32_t)kc * (16 * AST * 2) + np * 32);
                ldsm4t(vbl, smem_u + AVL + vb_off + (uint32_t)kc * (16 * AST * 2) + np * 32);
                mma_bf16(O[2*np],   ph, vbh[0], vbh[1]);
                mma_bf16(O[2*np],   ph, vbl[0], vbl[1]);
                mma_bf16(O[2*np],   pl, vbh[0], vbh[1]);
                mma_bf16(O[2*np+1], ph, vbh[2], vbh[3]);
                mma_bf16(O[2*np+1], ph, vbl[2], vbl[3]);
                mma_bf16(O[2*np+1], pl, vbh[2], vbh[3]);
            }
        }
    }

    // ---- finalize: write bf16 hi/lo output ----
    const float inv0 = 1.0f / l0;
    const float inv1 = 1.0f / l1;
    const size_t r0g = (size_t)(b*SEQ + q0 + w*16 + (lane >> 2));
#pragma unroll
    for (int n = 0; n < 16; ++n) {
        const int col = h*HD + 8*n + 2*(lane & 3);
        const float o1x = O[n][0] * inv0, o1y = O[n][1] * inv0;
        const float o2x = O[n][2] * inv1, o2y = O[n][3] * inv1;
        const uint32_t h1 = cvt2bf(o1y, o1x);
        const uint32_t l1p = cvt2bf(o1y - bfhi(h1), o1x - bflo(h1));
        const uint32_t h2 = cvt2bf(o2y, o2x);
        const uint32_t l2p = cvt2bf(o2y - bfhi(h2), o2x - bflo(h2));
        *(uint32_t*)&a_h[r0g * DIM + col]       = h1;
        *(uint32_t*)&a_l[r0g * DIM + col]       = l1p;
        *(uint32_t*)&a_h[(r0g + 8) * DIM + col] = h2;
        *(uint32_t*)&a_l[(r0g + 8) * DIM + col] = l2p;
    }
}

// ============================================================================
// Launcher
// ============================================================================
extern "C" void kernel_launch(void* const* d_in, const int* in_sizes, int n_in,
                              void* d_out, int out_size)
{
    const float* x  = (const float*)d_in[0];
    const float* fr = (const float*)d_in[1];
    const float* wq = (const float*)d_in[2];
    const float* bq = (const float*)d_in[3];
    const float* wk = (const float*)d_in[4];
    const float* bk = (const float*)d_in[5];
    const float* wv = (const float*)d_in[6];
    const float* bv = (const float*)d_in[7];
    const float* wo = (const float*)d_in[8];
    const float* bo = (const float*)d_in[9];
    const float* gq = (const float*)d_in[10];
    const float* gk = (const float*)d_in[11];
    float* out = (float*)d_out;

    (void)in_sizes; (void)n_in; (void)out_size;

    cudaFuncSetAttribute(gemm_qkv_kernel, cudaFuncAttributeMaxDynamicSharedMemorySize, GEMM_SMEM);
    cudaFuncSetAttribute(gemm_out_kernel, cudaFuncAttributeMaxDynamicSharedMemorySize, GEMM_SMEM);
    cudaFuncSetAttribute(attn_kernel, cudaFuncAttributeMaxDynamicSharedMemorySize, ATTN_SMEM);

    const int n4_x = MROWS * DIM / 4;
    const int n4_w = DIM * DIM / 4;

    split_x_kernel<<<n4_x / 256, 256>>>(x, n4_x);
    split_w_kernel<<<dim3(n4_w / 256, 4), 256>>>(wq, wk, wv, wo, n4_w);

    gemm_qkv_kernel<<<dim3(DIM/128, MROWS/128, 3), 256, GEMM_SMEM>>>(bq, bk, bv);

    rmsnorm_rope_kernel<<<dim3(MROWS, 2), 256>>>(fr, gq, gk);

    attn_kernel<<<dim3(SEQ/128, NH, BSZ), 256, ATTN_SMEM>>>();

    gemm_out_kernel<<<dim3(DIM/128, MROWS/128, 1), 256, GEMM_SMEM>>>(bo, out);
}

// round 16
// speedup vs baseline: 1.0015x; 1.0001x over previous
#include <cuda_runtime.h>
#include <cuda_bf16.h>
#include <cstdint>

#define DIM   2048
#define BSZ   2
#define SEQ   2048
#define NH    16
#define HD    128
#define MROWS (BSZ*SEQ)   /* 4096 */

typedef unsigned long long ull;

// ---- PTX helpers (baseline PTX only; no sm_103a-gated features) ----
__device__ __forceinline__ uint32_t smem_to_u32(const void* p) {
    uint32_t a;
    asm("{ .reg .u64 t; cvta.to.shared.u64 t, %1; cvt.u32.u64 %0, t; }" : "=r"(a) : "l"(p));
    return a;
}
__device__ __forceinline__ void ldsm4(uint32_t (&r)[4], uint32_t addr) {
    asm volatile("ldmatrix.sync.aligned.m8n8.x4.shared.b16 {%0,%1,%2,%3}, [%4];"
                 : "=r"(r[0]), "=r"(r[1]), "=r"(r[2]), "=r"(r[3]) : "r"(addr));
}
__device__ __forceinline__ void ldsm4t(uint32_t (&r)[4], uint32_t addr) {
    asm volatile("ldmatrix.sync.aligned.m8n8.x4.trans.shared.b16 {%0,%1,%2,%3}, [%4];"
                 : "=r"(r[0]), "=r"(r[1]), "=r"(r[2]), "=r"(r[3]) : "r"(addr));
}
__device__ __forceinline__ void mma_bf16(float (&d)[4], const uint32_t (&a)[4],
                                         uint32_t b0, uint32_t b1) {
    asm volatile("mma.sync.aligned.m16n8k16.row.col.f32.bf16.bf16.f32 "
                 "{%0,%1,%2,%3}, {%4,%5,%6,%7}, {%8,%9}, {%0,%1,%2,%3};"
                 : "+f"(d[0]), "+f"(d[1]), "+f"(d[2]), "+f"(d[3])
                 : "r"(a[0]), "r"(a[1]), "r"(a[2]), "r"(a[3]), "r"(b0), "r"(b1));
}
__device__ __forceinline__ uint32_t cvt2bf(float hi, float lo) {
    uint32_t r; asm("cvt.rn.bf16x2.f32 %0, %1, %2;" : "=r"(r) : "f"(hi), "f"(lo)); return r;
}
__device__ __forceinline__ float bflo(uint32_t p) { return __uint_as_float(p << 16); }
__device__ __forceinline__ float bfhi(uint32_t p) { return __uint_as_float(p & 0xffff0000u); }

__device__ __forceinline__ void cp_async16(uint32_t saddr, const void* gptr) {
    asm volatile("cp.async.cg.shared.global [%0], [%1], 16;" :: "r"(saddr), "l"(gptr));
}
#define CP_COMMIT()  asm volatile("cp.async.commit_group;" ::: "memory")
#define CP_WAIT(n)   asm volatile("cp.async.wait_group %0;" :: "n"(n) : "memory")

// ---- scratch (device globals: allocation-free rule) ----
__device__ float g_q[MROWS*DIM];
__device__ float g_k[MROWS*DIM];
__device__ __nv_bfloat16 x_h[MROWS*DIM],  x_l[MROWS*DIM];
__device__ __nv_bfloat16 wq_h[DIM*DIM], wq_l[DIM*DIM];
__device__ __nv_bfloat16 wk_h[DIM*DIM], wk_l[DIM*DIM];
__device__ __nv_bfloat16 wv_h[DIM*DIM], wv_l[DIM*DIM];
__device__ __nv_bfloat16 wo_h[DIM*DIM], wo_l[DIM*DIM];
__device__ __nv_bfloat16 q_h[MROWS*DIM], q_l[MROWS*DIM];
__device__ __nv_bfloat16 k_h[MROWS*DIM], k_l[MROWS*DIM];
__device__ __nv_bfloat16 v_h[MROWS*DIM], v_l[MROWS*DIM];
__device__ __nv_bfloat16 a_h[MROWS*DIM], a_l[MROWS*DIM];

__device__ __forceinline__ void split4(float4 v, uint2& hi, uint2& lo) {
    __nv_bfloat16 h0 = __float2bfloat16(v.x);
    __nv_bfloat16 h1 = __float2bfloat16(v.y);
    __nv_bfloat16 h2 = __float2bfloat16(v.z);
    __nv_bfloat16 h3 = __float2bfloat16(v.w);
    __nv_bfloat16 l0 = __float2bfloat16(v.x - __bfloat162float(h0));
    __nv_bfloat16 l1 = __float2bfloat16(v.y - __bfloat162float(h1));
    __nv_bfloat16 l2 = __float2bfloat16(v.z - __bfloat162float(h2));
    __nv_bfloat16 l3 = __float2bfloat16(v.w - __bfloat162float(h3));
    hi.x = ((uint32_t)__bfloat16_as_ushort(h1) << 16) | __bfloat16_as_ushort(h0);
    hi.y = ((uint32_t)__bfloat16_as_ushort(h3) << 16) | __bfloat16_as_ushort(h2);
    lo.x = ((uint32_t)__bfloat16_as_ushort(l1) << 16) | __bfloat16_as_ushort(l0);
    lo.y = ((uint32_t)__bfloat16_as_ushort(l3) << 16) | __bfloat16_as_ushort(l2);
}

// ============================================================================
// fp32 -> bf16 hi/lo split kernels
// ============================================================================
__global__ void __launch_bounds__(256) split_x_kernel(const float* __restrict__ src, int n4)
{
    const int i = blockIdx.x * blockDim.x + threadIdx.x;
    if (i >= n4) return;
    const float4 v = ((const float4*)src)[i];
    uint2 h, l; split4(v, h, l);
    ((uint2*)x_h)[i] = h;
    ((uint2*)x_l)[i] = l;
}

__global__ void __launch_bounds__(256) split_w_kernel(
    const float* __restrict__ wq, const float* __restrict__ wk,
    const float* __restrict__ wv, const float* __restrict__ wo, int n4)
{
    const int i = blockIdx.x * blockDim.x + threadIdx.x;
    if (i >= n4) return;
    const float* s;
    __nv_bfloat16 *hi, *lo;
    switch (blockIdx.y) {
        case 0: s = wq; hi = wq_h; lo = wq_l; break;
        case 1: s = wk; hi = wk_h; lo = wk_l; break;
        case 2: s = wv; hi = wv_h; lo = wv_l; break;
        default: s = wo; hi = wo_h; lo = wo_l; break;
    }
    const float4 v = ((const float4*)s)[i];
    uint2 h, l; split4(v, h, l);
    ((uint2*)hi)[i] = h;
    ((uint2*)lo)[i] = l;
}

// ============================================================================
// HMMA GEMM: C[M,N] = (Ah+Al)[M,K] @ (Bh+Bl)[N,K]^T + bias
// 128x128 CTA tile, 8 warps (2x4), 3 MMAs per product, fp32 accum.
// 2-stage cp.async pipeline; 2 CTAs/SM. BF16OUT writes hi/lo split directly.
// ============================================================================
#define BK        32
#define NSTAGES   (DIM / BK)            /* 64 */
#define LDS_B     40
#define TILE_BYT  (128 * LDS_B * 2)     /* 10240 */
#define OFF_AHI   0
#define OFF_ALO   (1 * TILE_BYT)
#define OFF_BHI   (2 * TILE_BYT)
#define OFF_BLO   (3 * TILE_BYT)
#define STG_BYT   (4 * TILE_BYT)        /* 40960 */
#define GEMM_SMEM (2 * STG_BYT)         /* 81920 -> 2 CTAs/SM */

__device__ __forceinline__ void gemm_issue(uint32_t dstbase,
    const __nv_bfloat16* __restrict__ Ah, const __nv_bfloat16* __restrict__ Al,
    const __nv_bfloat16* __restrict__ Bh, const __nv_bfloat16* __restrict__ Bl,
    int rowBase, int colBase, int kofs, int tid)
{
#pragma unroll
    for (int i = 0; i < 2; ++i) {
        const int f = i * 256 + tid;
        const int r = f >> 2, c = f & 3;
        const uint32_t d = dstbase + (uint32_t)r * (LDS_B * 2) + (uint32_t)c * 16;
        const size_t gA = (size_t)(rowBase + r) * DIM + kofs + c * 8;
        const size_t gB = (size_t)(colBase + r) * DIM + kofs + c * 8;
        cp_async16(d + OFF_AHI, Ah + gA);
        cp_async16(d + OFF_ALO, Al + gA);
        cp_async16(d + OFF_BHI, Bh + gB);
        cp_async16(d + OFF_BLO, Bl + gB);
    }
    CP_COMMIT();
}

template<bool BF16OUT>
__device__ __forceinline__ void gemm_tc_core(
    const __nv_bfloat16* __restrict__ Ah, const __nv_bfloat16* __restrict__ Al,
    const __nv_bfloat16* __restrict__ Bh, const __nv_bfloat16* __restrict__ Bl,
    const float* __restrict__ bias, float* __restrict__ C,
    __nv_bfloat16* __restrict__ Ch, __nv_bfloat16* __restrict__ Cl)
{
    extern __shared__ char smem[];
    const uint32_t smem_u = smem_to_u32(smem);
    const int tid  = threadIdx.x;
    const int lane = tid & 31;
    const int wid  = tid >> 5;
    const int wm   = wid & 1;
    const int wn   = wid >> 1;

    const int rowBase = blockIdx.y * 128;
    const int colBase = blockIdx.x * 128;

    const uint32_t a_off = (uint32_t)(wm * 64 + (lane & 15)) * (LDS_B * 2)
                         + (uint32_t)((lane >> 4) * 8) * 2;
    const uint32_t b_off = (uint32_t)(wn * 32 + ((lane >> 4) & 1) * 8 + (lane & 7)) * (LDS_B * 2)
                         + (uint32_t)(((lane >> 3) & 1) * 8) * 2;

    float acc[4][4][4];
#pragma unroll
    for (int t = 0; t < 4; ++t)
#pragma unroll
        for (int n = 0; n < 4; ++n)
#pragma unroll
            for (int e = 0; e < 4; ++e) acc[t][n][e] = 0.0f;

    gemm_issue(smem_u,           Ah, Al, Bh, Bl, rowBase, colBase, 0,  tid);
    gemm_issue(smem_u + STG_BYT, Ah, Al, Bh, Bl, rowBase, colBase, BK, tid);

    for (int s = 0; s < NSTAGES; ++s) {
        CP_WAIT(1);
        __syncthreads();

        const uint32_t cb = smem_u + (uint32_t)(s & 1) * STG_BYT;
#pragma unroll
        for (int ks = 0; ks < 2; ++ks) {
            uint32_t ah[4][4], al[4][4], bh[2][4], bl[2][4];
#pragma unroll
            for (int t = 0; t < 4; ++t) {
                ldsm4(ah[t], cb + OFF_AHI + a_off + (uint32_t)t * (16 * LDS_B * 2) + ks * 32);
                ldsm4(al[t], cb + OFF_ALO + a_off + (uint32_t)t * (16 * LDS_B * 2) + ks * 32);
            }
#pragma unroll
            for (int p = 0; p < 2; ++p) {
                ldsm4(bh[p], cb + OFF_BHI + b_off + (uint32_t)p * (16 * LDS_B * 2) + ks * 32);
                ldsm4(bl[p], cb + OFF_BLO + b_off + (uint32_t)p * (16 * LDS_B * 2) + ks * 32);
            }
#pragma unroll
            for (int t = 0; t < 4; ++t) {
#pragma unroll
                for (int n = 0; n < 4; ++n) {
                    const int p = n >> 1, sub = n & 1;
                    mma_bf16(acc[t][n], ah[t], bh[p][sub * 2], bh[p][sub * 2 + 1]);
                    mma_bf16(acc[t][n], ah[t], bl[p][sub * 2], bl[p][sub * 2 + 1]);
                    mma_bf16(acc[t][n], al[t], bh[p][sub * 2], bh[p][sub * 2 + 1]);
                }
            }
        }

        __syncthreads();
        if (s + 2 < NSTAGES)
            gemm_issue(smem_u + (uint32_t)(s & 1) * STG_BYT, Ah, Al, Bh, Bl,
                       rowBase, colBase, (s + 2) * BK, tid);
        else
            CP_COMMIT();
    }

#pragma unroll
    for (int t = 0; t < 4; ++t) {
        const int r1 = rowBase + wm * 64 + t * 16 + (lane >> 2);
#pragma unroll
        for (int n = 0; n < 4; ++n) {
            const int col = colBase + wn * 32 + n * 8 + (lane & 3) * 2;
            const float2 b2 = *(const float2*)&bias[col];
            const float o1x = acc[t][n][0] + b2.x, o1y = acc[t][n][1] + b2.y;
            const float o2x = acc[t][n][2] + b2.x, o2y = acc[t][n][3] + b2.y;
            if (!BF16OUT) {
                float2 o1, o2;
                o1.x = o1x; o1.y = o1y; o2.x = o2x; o2.y = o2y;
                *(float2*)&C[(size_t)r1 * DIM + col]       = o1;
                *(float2*)&C[(size_t)(r1 + 8) * DIM + col] = o2;
            } else {
                const uint32_t h1 = cvt2bf(o1y, o1x);
                const uint32_t l1 = cvt2bf(o1y - bfhi(h1), o1x - bflo(h1));
                const uint32_t h2 = cvt2bf(o2y, o2x);
                const uint32_t l2 = cvt2bf(o2y - bfhi(h2), o2x - bflo(h2));
                *(uint32_t*)&Ch[(size_t)r1 * DIM + col]       = h1;
                *(uint32_t*)&Cl[(size_t)r1 * DIM + col]       = l1;
                *(uint32_t*)&Ch[(size_t)(r1 + 8) * DIM + col] = h2;
                *(uint32_t*)&Cl[(size_t)(r1 + 8) * DIM + col] = l2;
            }
        }
    }
}

__global__ void __launch_bounds__(256, 2) gemm_qkv_kernel(
    const float* __restrict__ bq, const float* __restrict__ bk, const float* __restrict__ bv)
{
    if (blockIdx.z == 0)
        gemm_tc_core<false>(x_h, x_l, wq_h, wq_l, bq, g_q, nullptr, nullptr);
    else if (blockIdx.z == 1)
        gemm_tc_core<false>(x_h, x_l, wk_h, wk_l, bk, g_k, nullptr, nullptr);
    else
        gemm_tc_core<true>(x_h, x_l, wv_h, wv_l, bv, nullptr, v_h, v_l);
}

__global__ void __launch_bounds__(256, 2) gemm_out_kernel(
    const float* __restrict__ bo, float* __restrict__ out)
{
    gemm_tc_core<false>(a_h, a_l, wo_h, wo_l, bo, out, nullptr, nullptr);
}

// ============================================================================
// Fused RMSNorm(+gain) + RoPE. Reads g_q/g_k fp32, writes bf16 hi/lo pairs.
// ============================================================================
__global__ void __launch_bounds__(256) rmsnorm_rope_kernel(
    const float* __restrict__ freqs, const float* __restrict__ gq, const float* __restrict__ gk)
{
    const int row = blockIdx.x;
    const int s = row & (SEQ - 1);
    const float* xb = (blockIdx.y == 0 ? g_q : g_k) + (size_t)row * DIM;
    __nv_bfloat16* oh = (blockIdx.y == 0 ? q_h : k_h) + (size_t)row * DIM;
    __nv_bfloat16* ol = (blockIdx.y == 0 ? q_l : k_l) + (size_t)row * DIM;
    const float* g = (blockIdx.y == 0) ? gq : gk;
    const int tid = threadIdx.x;
    const int base = tid * 8;

    const float4 u = *(const float4*)(xb + base);
    const float4 w = *(const float4*)(xb + base + 4);
    float ss = u.x*u.x + u.y*u.y + u.z*u.z + u.w*u.w
             + w.x*w.x + w.y*w.y + w.z*w.z + w.w*w.w;
#pragma unroll
    for (int m = 16; m > 0; m >>= 1) ss += __shfl_xor_sync(0xffffffffu, ss, m);
    __shared__ float red[8];
    if ((tid & 31) == 0) red[tid >> 5] = ss;
    __syncthreads();
    const float tot = red[0]+red[1]+red[2]+red[3]+red[4]+red[5]+red[6]+red[7];
    const float rinv = rsqrtf(tot * (1.0f/DIM) + 1e-6f);

    const float4 g0 = *(const float4*)(g + base);
    const float4 g1 = *(const float4*)(g + base + 4);
    float y[8] = {u.x*rinv*g0.x, u.y*rinv*g0.y, u.z*rinv*g0.z, u.w*rinv*g0.w,
                  w.x*rinv*g1.x, w.y*rinv*g1.y, w.z*rinv*g1.z, w.w*rinv*g1.w};

    const float* fr = freqs + (size_t)s * HD;
    float o[8];
#pragma unroll
    for (int p = 0; p < 4; ++p) {
        const int col = base + 2*p;
        const int jj = (col & (HD - 1)) >> 1;
        const float cr = fr[2*jj], ci = fr[2*jj + 1];
        const float xr = y[2*p], xi = y[2*p + 1];
        o[2*p]     = xr*cr - xi*ci;
        o[2*p + 1] = xr*ci + xi*cr;
    }
    float4 r0; r0.x = o[0]; r0.y = o[1]; r0.z = o[2]; r0.w = o[3];
    float4 r1; r1.x = o[4]; r1.y = o[5]; r1.z = o[6]; r1.w = o[7];
    uint2 h, l;
    split4(r0, h, l);
    *(uint2*)(oh + base)     = h;
    *(uint2*)(ol + base)     = l;
    split4(r1, h, l);
    *(uint2*)(oh + base + 4) = h;
    *(uint2*)(ol + base + 4) = l;
}

// ============================================================================
// HMMA flash attention. 128 q-rows/CTA, 128-kv tiles.
// Q fragments live in registers (loaded straight from gmem, A-frag layout).
// Smem: K double-buffered (hi/lo) + V single (hi/lo) = 6 tiles.
// K_{i+1} load overlaps softmax+PV_i; V_i load overlaps QK_i.
// ============================================================================
#define AST   136                        /* halves per smem row */
#define ATILE_BYT (128 * AST * 2)        /* 34816 */
/* K buf0: [0,2T), K buf1: [2T,4T), V: [4T,6T)  (each pair = hi then lo) */
#define AVH  (4 * ATILE_BYT)
#define AVL  (5 * ATILE_BYT)
#define ATTN_SMEM (6 * ATILE_BYT)        /* 208896 */

__device__ __forceinline__ void attn_issue(uint32_t dstH, uint32_t dstL,
    const __nv_bfloat16* __restrict__ srcH, const __nv_bfloat16* __restrict__ srcL,
    size_t gbase, int tid)
{
#pragma unroll
    for (int i = 0; i < 8; ++i) {
        const int f = i * 256 + tid;
        const int r = f >> 4, c = f & 15;
        const uint32_t d = (uint32_t)r * (AST * 2) + (uint32_t)c * 16;
        const size_t gsrc = gbase + (size_t)r * DIM + c * 8;
        cp_async16(dstH + d, srcH + gsrc);
        cp_async16(dstL + d, srcL + gsrc);
    }
    CP_COMMIT();
}

__global__ void __launch_bounds__(256) attn_kernel()
{
    extern __shared__ char smh[];
    const uint32_t smem_u = smem_to_u32(smh);
    const int tid  = threadIdx.x;
    const int lane = tid & 31;
    const int w    = tid >> 5;
    const int b    = blockIdx.z;
    const int h    = blockIdx.y;
    const int q0   = blockIdx.x * 128;

    const size_t krow0 = (size_t)(b*SEQ) * DIM + h*HD;

    // ---- prologue: issue K tile 0 into K buf0 ----
    attn_issue(smem_u, smem_u + ATILE_BYT, k_h, k_l, krow0, tid);

    // ---- Q fragments -> registers (m16n8k16 A layout) ----
    // lane: row r = lane>>2 (and +8), k-pair col c0 = (lane&3)*2 (and +8)
    uint32_t qh[8][4], ql[8][4];
    {
        const size_t qbase = (size_t)(b*SEQ + q0 + w*16) * DIM + h*HD;
        const int r0 = lane >> 2;
        const int c0 = (lane & 3) * 2;
#pragma unroll
        for (int kc = 0; kc < 8; ++kc) {
            const size_t k0 = qbase + kc * 16 + c0;
            qh[kc][0] = *(const uint32_t*)&q_h[k0 + (size_t)r0 * DIM];
            qh[kc][1] = *(const uint32_t*)&q_h[k0 + (size_t)(r0 + 8) * DIM];
            qh[kc][2] = *(const uint32_t*)&q_h[k0 + 8 + (size_t)r0 * DIM];
            qh[kc][3] = *(const uint32_t*)&q_h[k0 + 8 + (size_t)(r0 + 8) * DIM];
            ql[kc][0] = *(const uint32_t*)&q_l[k0 + (size_t)r0 * DIM];
            ql[kc][1] = *(const uint32_t*)&q_l[k0 + (size_t)(r0 + 8) * DIM];
            ql[kc][2] = *(const uint32_t*)&q_l[k0 + 8 + (size_t)r0 * DIM];
            ql[kc][3] = *(const uint32_t*)&q_l[k0 + 8 + (size_t)(r0 + 8) * DIM];
        }
    }

    const uint32_t kb_off = ((uint32_t)(((lane >> 4) & 1) * 8 + (lane & 7)) * AST
                           + (uint32_t)(((lane >> 3) & 1) * 8)) * 2;
    const uint32_t vb_off = ((uint32_t)(((lane >> 3) & 1) * 8 + (lane & 7)) * AST
                           + (uint32_t)(((lane >> 4) & 1) * 8)) * 2;

    float O[16][4];
#pragma unroll
    for (int n = 0; n < 16; ++n)
#pragma unroll
        for (int e = 0; e < 4; ++e) O[n][e] = 0.0f;
    float mq0 = -1e30f, mq1 = -1e30f, l0 = 0.0f, l1 = 0.0f;

    const float Cs = 0.12754276931699657f;   // (1/sqrt(128)) * log2(e)

    for (int kt = 0; kt < SEQ / 128; ++kt) {
        const size_t krow = krow0 + (size_t)(kt * 128) * DIM;

        CP_WAIT(0);        // K_kt resident (V_{kt-1} completed earlier)
        __syncthreads();   // K visible to all; all warps past PV_{kt-1}

        // V_kt load overlaps QK
        attn_issue(smem_u + AVH, smem_u + AVL, v_h, v_l, krow, tid);

        // ---- scores over 128 kv cols (K from buffer kt&1) ----
        const uint32_t kbase = smem_u + (uint32_t)(kt & 1) * (2 * ATILE_BYT);
        float acc[16][4];
#pragma unroll
        for (int n = 0; n < 16; ++n)
#pragma unroll
            for (int e = 0; e < 4; ++e) acc[n][e] = 0.0f;

#pragma unroll
        for (int kc = 0; kc < 8; ++kc) {
#pragma unroll
            for (int np = 0; np < 8; ++np) {
                uint32_t kbh[4], kbl[4];
                ldsm4(kbh, kbase + kb_off + (uint32_t)np * (16 * AST * 2) + kc * 32);
                ldsm4(kbl, kbase + ATILE_BYT + kb_off + (uint32_t)np * (16 * AST * 2) + kc * 32);
                mma_bf16(acc[2*np],   qh[kc], kbh[0], kbh[1]);
                mma_bf16(acc[2*np],   qh[kc], kbl[0], kbl[1]);
                mma_bf16(acc[2*np],   ql[kc], kbh[0], kbh[1]);
                mma_bf16(acc[2*np+1], qh[kc], kbh[2], kbh[3]);
                mma_bf16(acc[2*np+1], qh[kc], kbl[2], kbl[3]);
                mma_bf16(acc[2*np+1], ql[kc], kbh[2], kbh[3]);
            }
        }

        // K_{kt+1} load overlaps softmax + PV (other K buffer; safe: all warps
        // past QK_{kt-1} via this iteration's top sync)
        if (kt + 1 < SEQ / 128) {
            attn_issue(smem_u + (uint32_t)((kt + 1) & 1) * (2 * ATILE_BYT),
                       smem_u + (uint32_t)((kt + 1) & 1) * (2 * ATILE_BYT) + ATILE_BYT,
                       k_h, k_l, krow + 128 * DIM, tid);
        } else {
            CP_COMMIT();
        }

        // ---- online softmax ----
        float pm0 = -1e30f, pm1 = -1e30f;
#pragma unroll
        for (int n = 0; n < 16; ++n) {
            pm0 = fmaxf(pm0, fmaxf(acc[n][0], acc[n][1]));
            pm1 = fmaxf(pm1, fmaxf(acc[n][2], acc[n][3]));
        }
        pm0 = fmaxf(pm0, __shfl_xor_sync(0xffffffffu, pm0, 1));
        pm0 = fmaxf(pm0, __shfl_xor_sync(0xffffffffu, pm0, 2));
        pm1 = fmaxf(pm1, __shfl_xor_sync(0xffffffffu, pm1, 1));
        pm1 = fmaxf(pm1, __shfl_xor_sync(0xffffffffu, pm1, 2));

        const float M0 = fmaxf(mq0, pm0 * Cs);
        const float M1 = fmaxf(mq1, pm1 * Cs);
        const float corr0 = exp2f(mq0 - M0);
        const float corr1 = exp2f(mq1 - M1);
        mq0 = M0; mq1 = M1;

        float rs0 = 0.0f, rs1 = 0.0f;
#pragma unroll
        for (int n = 0; n < 16; ++n) {
            acc[n][0] = exp2f(fmaf(acc[n][0], Cs, -M0));
            acc[n][1] = exp2f(fmaf(acc[n][1], Cs, -M0));
            acc[n][2] = exp2f(fmaf(acc[n][2], Cs, -M1));
            acc[n][3] = exp2f(fmaf(acc[n][3], Cs, -M1));
            rs0 += acc[n][0] + acc[n][1];
            rs1 += acc[n][2] + acc[n][3];
        }
        rs0 += __shfl_xor_sync(0xffffffffu, rs0, 1);
        rs0 += __shfl_xor_sync(0xffffffffu, rs0, 2);
        rs1 += __shfl_xor_sync(0xffffffffu, rs1, 1);
        rs1 += __shfl_xor_sync(0xffffffffu, rs1, 2);
        l0 = l0 * corr0 + rs0;
        l1 = l1 * corr1 + rs1;

#pragma unroll
        for (int n = 0; n < 16; ++n) {
            O[n][0] *= corr0; O[n][1] *= corr0;
            O[n][2] *= corr1; O[n][3] *= corr1;
        }

        CP_WAIT(1);        // V_kt resident (K_{kt+1} may still be in flight)
        __syncthreads();

        // ---- O += P @ V ----
#pragma unroll
        for (int kc = 0; kc < 8; ++kc) {
            uint32_t ph[4], pl[4];
            ph[0] = cvt2bf(acc[2*kc][1],   acc[2*kc][0]);
            ph[1] = cvt2bf(acc[2*kc][3],   acc[2*kc][2]);
            ph[2] = cvt2bf(acc[2*kc+1][1], acc[2*kc+1][0]);
            ph[3] = cvt2bf(acc[2*kc+1][3], acc[2*kc+1][2]);
            {
                float e0 = acc[2*kc][0]   - bflo(ph[0]);
                float e1 = acc[2*kc][1]   - bfhi(ph[0]);
                pl[0] = cvt2bf(e1, e0);
                e0 = acc[2*kc][2]   - bflo(ph[1]);
                e1 = acc[2*kc][3]   - bfhi(ph[1]);
                pl[1] = cvt2bf(e1, e0);
                e0 = acc[2*kc+1][0] - bflo(ph[2]);
                e1 = acc[2*kc+1][1] - bfhi(ph[2]);
                pl[2] = cvt2bf(e1, e0);
                e0 = acc[2*kc+1][2] - bflo(ph[3]);
                e1 = acc[2*kc+1][3] - bfhi(ph[3]);
                pl[3] = cvt2bf(e1, e0);
            }
#pragma unroll
            for (int np = 0; np < 8; ++np) {
                uint32_t vbh[4], vbl[4];
                ldsm4t(vbh, smem_u + AVH + vb_off + (uint32_t)kc * (16 * AST * 2) + np * 32);
                ldsm4t(vbl, smem_u + AVL + vb_off + (uint32_t)kc * (16 * AST * 2) + np * 32);
                mma_bf16(O[2*np],   ph, vbh[0], vbh[1]);
                mma_bf16(O[2*np],   ph, vbl[0], vbl[1]);
                mma_bf16(O[2*np],   pl, vbh[0], vbh[1]);
                mma_bf16(O[2*np+1], ph, vbh[2], vbh[3]);
                mma_bf16(O[2*np+1], ph, vbl[2], vbl[3]);
                mma_bf16(O[2*np+1], pl, vbh[2], vbh[3]);
            }
        }
    }

    // ---- finalize: write bf16 hi/lo output ----
    const float inv0 = 1.0f / l0;
    const float inv1 = 1.0f / l1;
    const size_t r0g = (size_t)(b*SEQ + q0 + w*16 + (lane >> 2));
#pragma unroll
    for (int n = 0; n < 16; ++n) {
        const int col = h*HD + 8*n + 2*(lane & 3);
        const float o1x = O[n][0] * inv0, o1y = O[n][1] * inv0;
        const float o2x = O[n][2] * inv1, o2y = O[n][3] * inv1;
        const uint32_t h1 = cvt2bf(o1y, o1x);
        const uint32_t l1p = cvt2bf(o1y - bfhi(h1), o1x - bflo(h1));
        const uint32_t h2 = cvt2bf(o2y, o2x);
        const uint32_t l2p = cvt2bf(o2y - bfhi(h2), o2x - bflo(h2));
        *(uint32_t*)&a_h[r0g * DIM + col]       = h1;
        *(uint32_t*)&a_l[r0g * DIM + col]       = l1p;
        *(uint32_t*)&a_h[(r0g + 8) * DIM + col] = h2;
        *(uint32_t*)&a_l[(r0g + 8) * DIM + col] = l2p;
    }
}

// ============================================================================
// Launcher
// ============================================================================
extern "C" void kernel_launch(void* const* d_in, const int* in_sizes, int n_in,
                              void* d_out, int out_size)
{
    const float* x  = (const float*)d_in[0];
    const float* fr = (const float*)d_in[1];
    const float* wq = (const float*)d_in[2];
    const float* bq = (const float*)d_in[3];
    const float* wk = (const float*)d_in[4];
    const float* bk = (const float*)d_in[5];
    const float* wv = (const float*)d_in[6];
    const float* bv = (const float*)d_in[7];
    const float* wo = (const float*)d_in[8];
    const float* bo = (const float*)d_in[9];
    const float* gq = (const float*)d_in[10];
    const float* gk = (const float*)d_in[11];
    float* out = (float*)d_out;

    (void)in_sizes; (void)n_in; (void)out_size;

    cudaFuncSetAttribute(gemm_qkv_kernel, cudaFuncAttributeMaxDynamicSharedMemorySize, GEMM_SMEM);
    cudaFuncSetAttribute(gemm_out_kernel, cudaFuncAttributeMaxDynamicSharedMemorySize, GEMM_SMEM);
    cudaFuncSetAttribute(attn_kernel, cudaFuncAttributeMaxDynamicSharedMemorySize, ATTN_SMEM);

    const int n4_x = MROWS * DIM / 4;
    const int n4_w = DIM * DIM / 4;

    split_x_kernel<<<n4_x / 256, 256>>>(x, n4_x);
    split_w_kernel<<<dim3(n4_w / 256, 4), 256>>>(wq, wk, wv, wo, n4_w);

    gemm_qkv_kernel<<<dim3(DIM/128, MROWS/128, 3), 256, GEMM_SMEM>>>(bq, bk, bv);

    rmsnorm_rope_kernel<<<dim3(MROWS, 2), 256>>>(fr, gq, gk);

    attn_kernel<<<dim3(SEQ/128, NH, BSZ), 256, ATTN_SMEM>>>();

    gemm_out_kernel<<<dim3(DIM/128, MROWS/128, 1), 256, GEMM_SMEM>>>(bo, out);
}